// round 16
// baseline (speedup 1.0000x reference)
#include <cuda_runtime.h>
#include <cuda_fp16.h>
#include <cuda_bf16.h>
#include <cstdint>
#include <math.h>

#define SLEN 1024
#define BSZ  32
#define NH   8
#define NQKVB 1544   /* 8*(3*64+1) */
#define ROWS 32768   /* SLEN*BSZ */
#define NPAD1 1664   /* 13*128 */
#define NT1  13
#define NT2  4

typedef __nv_bfloat16 bf16;
typedef __half fp16;

// ------------------------------------------------------------------ scratch
__device__ float g_qkvb[(size_t)ROWS * NQKVB];
__device__ __align__(256) fp16 g_A1[(size_t)ROWS * 512];
__device__ __align__(256) fp16 g_A2[(size_t)ROWS * 512];
__device__ __align__(256) fp16 g_B1[(size_t)NPAD1 * 512];
__device__ __align__(256) fp16 g_B2[(size_t)512 * 512];

// ------------------------------------------------------------------ helpers
__device__ __forceinline__ uint32_t smem_u32(const void* p) {
    uint32_t a;
    asm("{ .reg .u64 t; cvta.to.shared.u64 t, %1; cvt.u32.u64 %0, t; }" : "=r"(a) : "l"(p));
    return a;
}
__device__ __forceinline__ void cp_async16(uint32_t dst, const void* src) {
    asm volatile("cp.async.cg.shared.global [%0], [%1], 16;" :: "r"(dst), "l"(src) : "memory");
}
__device__ __forceinline__ void ldmatrix_x4(uint32_t* r, uint32_t addr) {
    asm volatile("ldmatrix.sync.aligned.m8n8.x4.shared.b16 {%0,%1,%2,%3}, [%4];"
                 : "=r"(r[0]), "=r"(r[1]), "=r"(r[2]), "=r"(r[3]) : "r"(addr));
}
__device__ __forceinline__ void mma_bf16(float* c, const uint32_t* a, uint32_t b0, uint32_t b1) {
    asm volatile(
        "mma.sync.aligned.m16n8k16.row.col.f32.bf16.bf16.f32 "
        "{%0,%1,%2,%3}, {%4,%5,%6,%7}, {%8,%9}, {%0,%1,%2,%3};"
        : "+f"(c[0]), "+f"(c[1]), "+f"(c[2]), "+f"(c[3])
        : "r"(a[0]), "r"(a[1]), "r"(a[2]), "r"(a[3]), "r"(b0), "r"(b1));
}
__device__ __forceinline__ void mma_fp16(float* c, const uint32_t* a, uint32_t b0, uint32_t b1) {
    asm volatile(
        "mma.sync.aligned.m16n8k16.row.col.f32.f16.f16.f32 "
        "{%0,%1,%2,%3}, {%4,%5,%6,%7}, {%8,%9}, {%0,%1,%2,%3};"
        : "+f"(c[0]), "+f"(c[1]), "+f"(c[2]), "+f"(c[3])
        : "r"(a[0]), "r"(a[1]), "r"(a[2]), "r"(a[3]), "r"(b0), "r"(b1));
}

// ------------------------------------------------------------------ prep X: fused LN -> single fp16
__global__ __launch_bounds__(128) void prep_x_kernel(
    const float* __restrict__ x, const float* __restrict__ gamma, const float* __restrict__ lnb,
    fp16* __restrict__ A)
{
    int row = blockIdx.x, tid = threadIdx.x;
    float4 v = *(const float4*)(x + (size_t)row * 512 + tid * 4);
    float s  = (v.x + v.y) + (v.z + v.w);
    float s2 = (v.x * v.x + v.y * v.y) + (v.z * v.z + v.w * v.w);
#pragma unroll
    for (int off = 16; off > 0; off >>= 1) {
        s  += __shfl_xor_sync(0xffffffffu, s,  off);
        s2 += __shfl_xor_sync(0xffffffffu, s2, off);
    }
    __shared__ float as_[4], aq_[4];
    int w = tid >> 5, l = tid & 31;
    if (l == 0) { as_[w] = s; aq_[w] = s2; }
    __syncthreads();
    float ts = (as_[0] + as_[1]) + (as_[2] + as_[3]);
    float tq = (aq_[0] + aq_[1]) + (aq_[2] + aq_[3]);
    float m  = ts * (1.f / 512.f);
    float ri = rsqrtf(tq * (1.f / 512.f) - m * m + 1e-5f);

    float4 g = *(const float4*)(gamma + tid * 4);
    float4 b = *(const float4*)(lnb   + tid * 4);
    float n0 = (v.x - m) * ri * g.x + b.x;
    float n1 = (v.y - m) * ri * g.y + b.y;
    float n2 = (v.z - m) * ri * g.z + b.z;
    float n3 = (v.w - m) * ri * g.w + b.w;

    size_t o = (size_t)row * 512 + tid * 4;
    *(__half2*)(A + o)     = __floats2half2_rn(n0, n1);
    *(__half2*)(A + o + 2) = __floats2half2_rn(n2, n3);
}

// ------------------------------------------------------------------ prep B (merged): transpose both weights -> [Npad][512], fp16
// blockIdx.x < 52 -> w_slow tile; else w_out tile (52..67)
__global__ __launch_bounds__(256) void prep_b_kernel(
    const float* __restrict__ W1, const float* __restrict__ W2,
    fp16* __restrict__ B1o, fp16* __restrict__ B2o)
{
    __shared__ float t[32][33];
    int bx = blockIdx.x, kt = blockIdx.y;
    const float* W; fp16* Bo; int N; int nt;
    if (bx < 52) { W = W1; Bo = B1o; N = NQKVB; nt = bx; }
    else         { W = W2; Bo = B2o; N = 512;   nt = bx - 52; }
    int tx = threadIdx.x & 31, ty = threadIdx.x >> 5;  // 32 x 8
#pragma unroll
    for (int r = 0; r < 4; r++) {
        int k = kt * 32 + ty + r * 8;
        int n = nt * 32 + tx;
        t[tx][ty + r * 8] = (n < N) ? W[(size_t)k * N + n] : 0.f;
    }
    __syncthreads();
#pragma unroll
    for (int r = 0; r < 4; r++) {
        int n = nt * 32 + ty + r * 8;
        int k = kt * 32 + tx;
        Bo[(size_t)n * 512 + k] = __float2half_rn(t[ty + r * 8][tx]);
    }
}

// ------------------------------------------------------------------ fp16 single-MMA tensor-core GEMM
#define STG_ARR 10240
#define STG_SZ  20480
#define SMEM_DYN (2 * STG_SZ)

__global__ __launch_bounds__(256) void gemm_kernel(
    const fp16* __restrict__ A, const fp16* __restrict__ B,
    float* __restrict__ C, const float* __restrict__ res, int N)
{
    extern __shared__ __align__(128) char smem[];
    uint32_t sb = smem_u32(smem);
    int tid = threadIdx.x, wid = tid >> 5, lane = tid & 31;
    int ntile = blockIdx.x, mtile = blockIdx.y;
    int wm = wid & 3, wn = wid >> 2;

    const fp16* srcs[2];
    srcs[0] = A + (size_t)mtile * 128 * 512;
    srcs[1] = B + (size_t)ntile * 128 * 512;

    float c[2][8][4];
#pragma unroll
    for (int i = 0; i < 2; i++)
#pragma unroll
        for (int j = 0; j < 8; j++)
#pragma unroll
            for (int q = 0; q < 4; q++) c[i][j][q] = 0.f;

    auto load_stage = [&](int kb, int buf) {
#pragma unroll
        for (int i = 0; i < 4; i++) {
            int id = tid + i * 256;
            int arr = id >> 9, rem = id & 511, row = rem >> 2, ch = rem & 3;
            const char* src = (const char*)(srcs[arr] + (size_t)row * 512 + kb * 32) + ch * 16;
            uint32_t dst = sb + buf * STG_SZ + arr * STG_ARR + row * 80 + ch * 16;
            cp_async16(dst, src);
        }
        asm volatile("cp.async.commit_group;" ::: "memory");
    };

    load_stage(0, 0);

    for (int kb = 0; kb < 16; kb++) {
        int buf = kb & 1;
        if (kb + 1 < 16) {
            load_stage(kb + 1, buf ^ 1);
            asm volatile("cp.async.wait_group 1;" ::: "memory");
        } else {
            asm volatile("cp.async.wait_group 0;" ::: "memory");
        }
        __syncthreads();

        uint32_t base = sb + buf * STG_SZ;
#pragma unroll
        for (int ks = 0; ks < 2; ks++) {
            uint32_t a_[2][4], b_[4][4];
#pragma unroll
            for (int mi = 0; mi < 2; mi++) {
                uint32_t row = wm * 32 + mi * 16 + (lane & 15);
                uint32_t col = ks * 32 + ((lane >> 4) & 1) * 16;
                ldmatrix_x4(a_[mi], base + row * 80 + col);
            }
#pragma unroll
            for (int p = 0; p < 4; p++) {
                uint32_t row = wn * 64 + p * 16 + (lane & 7) + ((lane >> 4) & 1) * 8;
                uint32_t col = ks * 32 + ((lane >> 3) & 1) * 16;
                ldmatrix_x4(b_[p], base + STG_ARR + row * 80 + col);
            }
#pragma unroll
            for (int mi = 0; mi < 2; mi++)
#pragma unroll
                for (int p = 0; p < 4; p++)
#pragma unroll
                    for (int hf = 0; hf < 2; hf++) {
                        int nb = p * 2 + hf;
                        mma_fp16(c[mi][nb], a_[mi], b_[p][hf * 2], b_[p][hf * 2 + 1]);
                    }
        }
        __syncthreads();
    }

    int grow = mtile * 128 + wm * 32;
    int gcol0 = ntile * 128 + wn * 64;
#pragma unroll
    for (int mi = 0; mi < 2; mi++) {
        int r0 = grow + mi * 16 + (lane >> 2);
#pragma unroll
        for (int nb = 0; nb < 8; nb++) {
            int col = gcol0 + nb * 8 + (lane & 3) * 2;
            if (col < N) {
                float2 v0 = make_float2(c[mi][nb][0], c[mi][nb][1]);
                float2 v1 = make_float2(c[mi][nb][2], c[mi][nb][3]);
                if (res) {
                    float2 q0 = *(const float2*)(res + (size_t)r0 * N + col);
                    float2 q1 = *(const float2*)(res + (size_t)(r0 + 8) * N + col);
                    v0.x += q0.x; v0.y += q0.y; v1.x += q1.x; v1.y += q1.y;
                }
                *(float2*)(C + (size_t)r0 * N + col)       = v0;
                *(float2*)(C + (size_t)(r0 + 8) * N + col) = v1;
            }
        }
    }
}

// ------------------------------------------------------------------ chunked delta-rule scan (WY form), C=64
// Activations (elu+1 + sum-norm on q,k; sigmoid on beta) FUSED into phase 0.
#define BST  72        // bf16 smem row stride (elements)
#define BSTB 144       // bytes
#define FST  68        // fp32 smem row stride (elements)

// smem byte offsets
#define OFF_S    0
#define OFF_A    17408
#define OFF_RU   34816
#define OFF_BETA 52224
#define OFF_KH   52480
#define OFF_KL   61696
#define OFF_KTH  70912
#define OFF_KTL  80128
#define OFF_QH   89344
#define OFF_QL   98560
#define OFF_MH   107776
#define OFF_ML   116992
#define OFF_SUH  126208
#define OFF_SUL  135424
#define SMEM_SCAN 144640

// 3-split 16x64x64 GEMM accumulate; A tile base (row m0 pre-added), B base (64 rows).
__device__ __forceinline__ void mma16x64_3split(
    uint32_t Ah, uint32_t Al, uint32_t Bh, uint32_t Bl, int lane, float c[8][4])
{
#pragma unroll
    for (int ks = 0; ks < 4; ks++) {
        uint32_t ah[4], al[4];
        uint32_t aoff = (uint32_t)(lane & 15) * BSTB + ks * 32 + ((lane >> 4) & 1) * 16;
        ldmatrix_x4(ah, Ah + aoff);
        ldmatrix_x4(al, Al + aoff);
#pragma unroll
        for (int p = 0; p < 4; p++) {
            uint32_t brow = p * 16 + (lane & 7) + ((lane >> 4) & 1) * 8;
            uint32_t boff = brow * BSTB + ks * 32 + ((lane >> 3) & 1) * 16;
            uint32_t bh[4], bl[4];
            ldmatrix_x4(bh, Bh + boff);
            ldmatrix_x4(bl, Bl + boff);
#pragma unroll
            for (int hf = 0; hf < 2; hf++) {
                int nb = p * 2 + hf;
                mma_bf16(c[nb], ah, bh[hf * 2], bh[hf * 2 + 1]);
                mma_bf16(c[nb], ah, bl[hf * 2], bl[hf * 2 + 1]);
                mma_bf16(c[nb], al, bh[hf * 2], bh[hf * 2 + 1]);
            }
        }
    }
}

__global__ __launch_bounds__(256) void scan_chunked_kernel() {
    extern __shared__ __align__(128) char smem[];
    uint32_t sb = smem_u32(smem);
    int bh = blockIdx.x;
    int b = bh >> 3, h = bh & 7;
    int tid = threadIdx.x, wid = tid >> 5, lane = tid & 31;

    float* sS    = (float*)(smem + OFF_S);
    float* sA    = (float*)(smem + OFF_A);
    float* sRU   = (float*)(smem + OFF_RU);
    float* sBeta = (float*)(smem + OFF_BETA);
    bf16* sKh  = (bf16*)(smem + OFF_KH);
    bf16* sKl  = (bf16*)(smem + OFF_KL);
    bf16* sKTh = (bf16*)(smem + OFF_KTH);
    bf16* sKTl = (bf16*)(smem + OFF_KTL);
    bf16* sQh  = (bf16*)(smem + OFF_QH);
    bf16* sQl  = (bf16*)(smem + OFF_QL);
    bf16* sMh  = (bf16*)(smem + OFF_MH);
    bf16* sMl  = (bf16*)(smem + OFF_ML);
    bf16* sSUh = (bf16*)(smem + OFF_SUH);
    bf16* sSUl = (bf16*)(smem + OFF_SUL);

    uint32_t aKh  = sb + OFF_KH,  aKl  = sb + OFF_KL;
    uint32_t aKTh = sb + OFF_KTH, aKTl = sb + OFF_KTL;
    uint32_t aQh  = sb + OFF_QH,  aQl  = sb + OFF_QL;
    uint32_t aMh  = sb + OFF_MH,  aMl  = sb + OFF_ML;
    uint32_t aSUh = sb + OFF_SUH, aSUl = sb + OFF_SUL;

    // zero state S
#pragma unroll
    for (int e = 0; e < 17; e++) {
        int idx = tid + e * 256;
        if (idx < 64 * FST) sS[idx] = 0.f;
    }
    __syncthreads();

    int jm = (wid & 3) * 16;           // warp tile m0
    int r0 = (lane >> 2);              // c-frag row within tile
    int col0 = (lane & 3) * 2;         // c-frag col within n8 tile

    for (int cc = 0; cc < 16; cc++) {
        // ---- phase 0: load raw K,Q,V,beta; apply activations; convert; S -> bf16 hi/lo
#pragma unroll
        for (int r8 = 0; r8 < 8; r8++) {
            int t = wid * 8 + r8;
            const float* src = g_qkvb + ((size_t)((cc * 64 + t) * 32 + b)) * NQKVB + h * 193;
            int j = lane * 2;
            // scalar loads (base offset h*193 may be odd -> no float2)
            float qx = src[j],       qy = src[j + 1];
            float kx = src[64 + j],  ky = src[64 + j + 1];
            float vx = src[128 + j], vy = src[128 + j + 1];

            // ---- fused activation: elu+1 then sum-normalize (warp allreduce)
            float eq0 = qx > 0.f ? qx + 1.f : expf(qx);
            float eq1 = qy > 0.f ? qy + 1.f : expf(qy);
            float ek0 = kx > 0.f ? kx + 1.f : expf(kx);
            float ek1 = ky > 0.f ? ky + 1.f : expf(ky);
            float sq = eq0 + eq1, sk = ek0 + ek1;
#pragma unroll
            for (int off = 16; off > 0; off >>= 1) {
                sq += __shfl_xor_sync(0xffffffffu, sq, off);
                sk += __shfl_xor_sync(0xffffffffu, sk, off);
            }
            float qinv = 1.f / sq, kinv = 1.f / sk;
            qx = eq0 * qinv; qy = eq1 * qinv;
            kx = ek0 * kinv; ky = ek1 * kinv;

            // q
            bf16 qh0 = __float2bfloat16_rn(qx);
            bf16 qh1 = __float2bfloat16_rn(qy);
            sQh[t * BST + j] = qh0;     sQh[t * BST + j + 1] = qh1;
            sQl[t * BST + j]     = __float2bfloat16_rn(qx - __bfloat162float(qh0));
            sQl[t * BST + j + 1] = __float2bfloat16_rn(qy - __bfloat162float(qh1));
            // k (+ transposed copy)
            bf16 kh0 = __float2bfloat16_rn(kx);
            bf16 kh1 = __float2bfloat16_rn(ky);
            bf16 kl0 = __float2bfloat16_rn(kx - __bfloat162float(kh0));
            bf16 kl1 = __float2bfloat16_rn(ky - __bfloat162float(kh1));
            sKh[t * BST + j] = kh0;     sKh[t * BST + j + 1] = kh1;
            sKl[t * BST + j] = kl0;     sKl[t * BST + j + 1] = kl1;
            sKTh[j * BST + t] = kh0;    sKTh[(j + 1) * BST + t] = kh1;
            sKTl[j * BST + t] = kl0;    sKTl[(j + 1) * BST + t] = kl1;
            // v (fp32 into RU)
            sRU[t * FST + j] = vx;      sRU[t * FST + j + 1] = vy;
            if (lane == 0) sBeta[t] = 1.f / (1.f + expf(-src[192]));
        }
        // S -> SUh/SUl
#pragma unroll
        for (int e = 0; e < 16; e++) {
            int idx = tid + e * 256;
            int i = idx >> 6, j = idx & 63;
            float v = sS[i * FST + j];
            bf16 hv = __float2bfloat16_rn(v);
            sSUh[i * BST + j] = hv;
            sSUl[i * BST + j] = __float2bfloat16_rn(v - __bfloat162float(hv));
        }
        __syncthreads();

        // ---- phase 1: KK->A (w0-3), QK->M (w4-7), KS->R (w0-3), QS->oc (w4-7)
        float oc[8][4];
#pragma unroll
        for (int nb = 0; nb < 8; nb++)
#pragma unroll
            for (int q = 0; q < 4; q++) oc[nb][q] = 0.f;

        {
            float c1[8][4];
#pragma unroll
            for (int nb = 0; nb < 8; nb++)
#pragma unroll
                for (int q = 0; q < 4; q++) c1[nb][q] = 0.f;

            if (wid < 4) {
                // KK = K K^T
                mma16x64_3split(aKh + jm * BSTB, aKl + jm * BSTB, aKh, aKl, lane, c1);
                int t1 = jm + r0, t2 = t1 + 8;
                float b1 = sBeta[t1], b2 = sBeta[t2];
#pragma unroll
                for (int nb = 0; nb < 8; nb++) {
                    int s0 = nb * 8 + col0;
                    sA[t1 * FST + s0]     = (s0     < t1) ? b1 * c1[nb][0] : 0.f;
                    sA[t1 * FST + s0 + 1] = (s0 + 1 < t1) ? b1 * c1[nb][1] : 0.f;
                    sA[t2 * FST + s0]     = (s0     < t2) ? b2 * c1[nb][2] : 0.f;
                    sA[t2 * FST + s0 + 1] = (s0 + 1 < t2) ? b2 * c1[nb][3] : 0.f;
                }
            } else {
                // QK -> M (masked s<=t), bf16 split
                mma16x64_3split(aQh + jm * BSTB, aQl + jm * BSTB, aKh, aKl, lane, c1);
                int t1 = jm + r0, t2 = t1 + 8;
#pragma unroll
                for (int nb = 0; nb < 8; nb++) {
                    int s0 = nb * 8 + col0;
#pragma unroll
                    for (int q = 0; q < 4; q++) {
                        int tt = (q >= 2) ? t2 : t1;
                        int ss = s0 + (q & 1);
                        float v = (ss <= tt) ? c1[nb][q] : 0.f;
                        bf16 hv = __float2bfloat16_rn(v);
                        sMh[tt * BST + ss] = hv;
                        sMl[tt * BST + ss] = __float2bfloat16_rn(v - __bfloat162float(hv));
                    }
                }
            }
            // second job
            if (wid < 4) {
                float c2[8][4];
#pragma unroll
                for (int nb = 0; nb < 8; nb++)
#pragma unroll
                    for (int q = 0; q < 4; q++) c2[nb][q] = 0.f;
                // KS = K S^T -> R = beta*(V - KS)
                mma16x64_3split(aKh + jm * BSTB, aKl + jm * BSTB, aSUh, aSUl, lane, c2);
                int t1 = jm + r0, t2 = t1 + 8;
                float b1 = sBeta[t1], b2 = sBeta[t2];
#pragma unroll
                for (int nb = 0; nb < 8; nb++) {
                    int i0 = nb * 8 + col0;
                    int x11 = t1 * FST + i0, x12 = x11 + 1;
                    int x21 = t2 * FST + i0, x22 = x21 + 1;
                    sRU[x11] = b1 * (sRU[x11] - c2[nb][0]);
                    sRU[x12] = b1 * (sRU[x12] - c2[nb][1]);
                    sRU[x21] = b2 * (sRU[x21] - c2[nb][2]);
                    sRU[x22] = b2 * (sRU[x22] - c2[nb][3]);
                }
            } else {
                // QS = Q S^T -> retained in oc
                mma16x64_3split(aQh + jm * BSTB, aQl + jm * BSTB, aSUh, aSUl, lane, oc);
            }
        }
        __syncthreads();

        // ---- phase 2: blocked forward substitution, U in-place in sRU
        {
            int tl = tid >> 4;           // 0..15
            int ib = (tid & 15) * 4;     // i base
            for (int blk = 0; blk < 4; blk++) {
                int T0 = blk * 16;
                if (blk > 0) {
                    int t = T0 + tl;
                    float4 acc = make_float4(0.f, 0.f, 0.f, 0.f);
                    for (int s = 0; s < T0; s++) {
                        float a = sA[t * FST + s];
                        float4 us = *(const float4*)&sRU[s * FST + ib];
                        acc.x += a * us.x; acc.y += a * us.y;
                        acc.z += a * us.z; acc.w += a * us.w;
                    }
                    float4 r = *(float4*)&sRU[t * FST + ib];
                    r.x -= acc.x; r.y -= acc.y; r.z -= acc.z; r.w -= acc.w;
                    *(float4*)&sRU[t * FST + ib] = r;
                }
                __syncthreads();
                if (wid == 0) {
                    float u0[16], u1[16];
#pragma unroll
                    for (int r = 0; r < 16; r++) {
                        int t = T0 + r;
                        float a0 = sRU[t * FST + lane];
                        float a1 = sRU[t * FST + lane + 32];
#pragma unroll
                        for (int s = 0; s < r; s++) {
                            float a = sA[t * FST + T0 + s];
                            a0 -= a * u0[s];
                            a1 -= a * u1[s];
                        }
                        u0[r] = a0; u1[r] = a1;
                        sRU[t * FST + lane] = a0;
                        sRU[t * FST + lane + 32] = a1;
                    }
                }
                __syncthreads();
            }
        }
        // U -> UT bf16 hi/lo (overlay on SU buffers; S bf16 no longer needed)
#pragma unroll
        for (int e = 0; e < 16; e++) {
            int idx = tid + e * 256;
            int s = idx >> 6, i = idx & 63;
            float v = sRU[s * FST + i];
            bf16 hv = __float2bfloat16_rn(v);
            sSUh[i * BST + s] = hv;
            sSUl[i * BST + s] = __float2bfloat16_rn(v - __bfloat162float(hv));
        }
        __syncthreads();

        // ---- phase 3: O = QS + M U (w4-7, write out fp16); dS = U^T K (w0-3)
        if (wid >= 4) {
            mma16x64_3split(aMh + jm * BSTB, aMl + jm * BSTB, aSUh, aSUl, lane, oc);
            int t1 = jm + r0, t2 = t1 + 8;
            size_t row1 = ((size_t)((cc * 64 + t1) * 32 + b)) * 512 + h * 64;
            size_t row2 = ((size_t)((cc * 64 + t2) * 32 + b)) * 512 + h * 64;
#pragma unroll
            for (int nb = 0; nb < 8; nb++) {
                int i0 = nb * 8 + col0;
#pragma unroll
                for (int q = 0; q < 4; q++) {
                    float o = oc[nb][q];
                    size_t addr = ((q >= 2) ? row2 : row1) + i0 + (q & 1);
                    g_A2[addr] = __float2half_rn(o);
                }
            }
        } else {
            float c3[8][4];
#pragma unroll
            for (int nb = 0; nb < 8; nb++)
#pragma unroll
                for (int q = 0; q < 4; q++) c3[nb][q] = 0.f;
            mma16x64_3split(aSUh + jm * BSTB, aSUl + jm * BSTB, aKTh, aKTl, lane, c3);
            int i1 = jm + r0, i2 = i1 + 8;
#pragma unroll
            for (int nb = 0; nb < 8; nb++) {
                int j0 = nb * 8 + col0;
                sS[i1 * FST + j0]     += c3[nb][0];
                sS[i1 * FST + j0 + 1] += c3[nb][1];
                sS[i2 * FST + j0]     += c3[nb][2];
                sS[i2 * FST + j0 + 1] += c3[nb][3];
            }
        }
        __syncthreads();
    }
}

// ------------------------------------------------------------------ launch
extern "C" void kernel_launch(void* const* d_in, const int* in_sizes, int n_in,
                              void* d_out, int out_size) {
    const float* x     = (const float*)d_in[0];
    const float* gamma = (const float*)d_in[1];
    const float* lnb   = (const float*)d_in[2];
    const float* wslow = (const float*)d_in[3];
    const float* wout  = (const float*)d_in[4];
    float* out = (float*)d_out;

    cudaFuncSetAttribute(gemm_kernel, cudaFuncAttributeMaxDynamicSharedMemorySize, SMEM_DYN);
    cudaFuncSetAttribute(scan_chunked_kernel, cudaFuncAttributeMaxDynamicSharedMemorySize, SMEM_SCAN);

    fp16 *A1, *A2, *B1, *B2;
    cudaGetSymbolAddress((void**)&A1, g_A1);
    cudaGetSymbolAddress((void**)&A2, g_A2);
    cudaGetSymbolAddress((void**)&B1, g_B1);
    cudaGetSymbolAddress((void**)&B2, g_B2);
    float* qkvb;
    cudaGetSymbolAddress((void**)&qkvb, g_qkvb);

    prep_x_kernel<<<ROWS, 128>>>(x, gamma, lnb, A1);
    prep_b_kernel<<<dim3(68, 16), 256>>>(wslow, wout, B1, B2);
    gemm_kernel<<<dim3(NT1, 256), 256, SMEM_DYN>>>(A1, B1, qkvb, nullptr, NQKVB);
    scan_chunked_kernel<<<BSZ * NH, 256, SMEM_SCAN>>>();
    gemm_kernel<<<dim3(NT2, 256), 256, SMEM_DYN>>>(A2, B2, out, x, 512);
}

// round 17
// speedup vs baseline: 1.3677x; 1.3677x over previous
#include <cuda_runtime.h>
#include <cuda_fp16.h>
#include <cstdint>
#include <math.h>

#define SLEN 1024
#define BSZ  32
#define NH   8
#define NQKVB 1544   /* 8*(3*64+1) */
#define ROWS 32768   /* SLEN*BSZ */
#define NPAD1 1664   /* 13*128 */
#define NT1  13
#define NT2  4

typedef __half fp16;

// ------------------------------------------------------------------ scratch
__device__ float g_qkvb[(size_t)ROWS * NQKVB];
__device__ __align__(256) fp16 g_A1[(size_t)ROWS * 512];
__device__ __align__(256) fp16 g_A2[(size_t)ROWS * 512];
__device__ __align__(256) fp16 g_B1[(size_t)NPAD1 * 512];
__device__ __align__(256) fp16 g_B2[(size_t)512 * 512];

// ------------------------------------------------------------------ helpers
__device__ __forceinline__ uint32_t smem_u32(const void* p) {
    uint32_t a;
    asm("{ .reg .u64 t; cvta.to.shared.u64 t, %1; cvt.u32.u64 %0, t; }" : "=r"(a) : "l"(p));
    return a;
}
__device__ __forceinline__ void cp_async16(uint32_t dst, const void* src) {
    asm volatile("cp.async.cg.shared.global [%0], [%1], 16;" :: "r"(dst), "l"(src) : "memory");
}
__device__ __forceinline__ void ldmatrix_x4(uint32_t* r, uint32_t addr) {
    asm volatile("ldmatrix.sync.aligned.m8n8.x4.shared.b16 {%0,%1,%2,%3}, [%4];"
                 : "=r"(r[0]), "=r"(r[1]), "=r"(r[2]), "=r"(r[3]) : "r"(addr));
}
__device__ __forceinline__ void mma_fp16(float* c, const uint32_t* a, uint32_t b0, uint32_t b1) {
    asm volatile(
        "mma.sync.aligned.m16n8k16.row.col.f32.f16.f16.f32 "
        "{%0,%1,%2,%3}, {%4,%5,%6,%7}, {%8,%9}, {%0,%1,%2,%3};"
        : "+f"(c[0]), "+f"(c[1]), "+f"(c[2]), "+f"(c[3])
        : "r"(a[0]), "r"(a[1]), "r"(a[2]), "r"(a[3]), "r"(b0), "r"(b1));
}

// ------------------------------------------------------------------ prep X: fused LN -> single fp16
__global__ __launch_bounds__(128) void prep_x_kernel(
    const float* __restrict__ x, const float* __restrict__ gamma, const float* __restrict__ lnb,
    fp16* __restrict__ A)
{
    int row = blockIdx.x, tid = threadIdx.x;
    float4 v = *(const float4*)(x + (size_t)row * 512 + tid * 4);
    float s  = (v.x + v.y) + (v.z + v.w);
    float s2 = (v.x * v.x + v.y * v.y) + (v.z * v.z + v.w * v.w);
#pragma unroll
    for (int off = 16; off > 0; off >>= 1) {
        s  += __shfl_xor_sync(0xffffffffu, s,  off);
        s2 += __shfl_xor_sync(0xffffffffu, s2, off);
    }
    __shared__ float as_[4], aq_[4];
    int w = tid >> 5, l = tid & 31;
    if (l == 0) { as_[w] = s; aq_[w] = s2; }
    __syncthreads();
    float ts = (as_[0] + as_[1]) + (as_[2] + as_[3]);
    float tq = (aq_[0] + aq_[1]) + (aq_[2] + aq_[3]);
    float m  = ts * (1.f / 512.f);
    float ri = rsqrtf(tq * (1.f / 512.f) - m * m + 1e-5f);

    float4 g = *(const float4*)(gamma + tid * 4);
    float4 b = *(const float4*)(lnb   + tid * 4);
    float n0 = (v.x - m) * ri * g.x + b.x;
    float n1 = (v.y - m) * ri * g.y + b.y;
    float n2 = (v.z - m) * ri * g.z + b.z;
    float n3 = (v.w - m) * ri * g.w + b.w;

    size_t o = (size_t)row * 512 + tid * 4;
    *(__half2*)(A + o)     = __floats2half2_rn(n0, n1);
    *(__half2*)(A + o + 2) = __floats2half2_rn(n2, n3);
}

// ------------------------------------------------------------------ prep B (merged): transpose both weights -> [Npad][512], fp16
__global__ __launch_bounds__(256) void prep_b_kernel(
    const float* __restrict__ W1, const float* __restrict__ W2,
    fp16* __restrict__ B1o, fp16* __restrict__ B2o)
{
    __shared__ float t[32][33];
    int bx = blockIdx.x, kt = blockIdx.y;
    const float* W; fp16* Bo; int N; int nt;
    if (bx < 52) { W = W1; Bo = B1o; N = NQKVB; nt = bx; }
    else         { W = W2; Bo = B2o; N = 512;   nt = bx - 52; }
    int tx = threadIdx.x & 31, ty = threadIdx.x >> 5;
#pragma unroll
    for (int r = 0; r < 4; r++) {
        int k = kt * 32 + ty + r * 8;
        int n = nt * 32 + tx;
        t[tx][ty + r * 8] = (n < N) ? W[(size_t)k * N + n] : 0.f;
    }
    __syncthreads();
#pragma unroll
    for (int r = 0; r < 4; r++) {
        int n = nt * 32 + ty + r * 8;
        int k = kt * 32 + tx;
        Bo[(size_t)n * 512 + k] = __float2half_rn(t[ty + r * 8][tx]);
    }
}

// ------------------------------------------------------------------ fp16 single-MMA tensor-core GEMM
#define STG_ARR 10240
#define STG_SZ  20480
#define SMEM_DYN (2 * STG_SZ)

__global__ __launch_bounds__(256) void gemm_kernel(
    const fp16* __restrict__ A, const fp16* __restrict__ B,
    float* __restrict__ C, const float* __restrict__ res, int N)
{
    extern __shared__ __align__(128) char smem[];
    uint32_t sb = smem_u32(smem);
    int tid = threadIdx.x, wid = tid >> 5, lane = tid & 31;
    int ntile = blockIdx.x, mtile = blockIdx.y;
    int wm = wid & 3, wn = wid >> 2;

    const fp16* srcs[2];
    srcs[0] = A + (size_t)mtile * 128 * 512;
    srcs[1] = B + (size_t)ntile * 128 * 512;

    float c[2][8][4];
#pragma unroll
    for (int i = 0; i < 2; i++)
#pragma unroll
        for (int j = 0; j < 8; j++)
#pragma unroll
            for (int q = 0; q < 4; q++) c[i][j][q] = 0.f;

    auto load_stage = [&](int kb, int buf) {
#pragma unroll
        for (int i = 0; i < 4; i++) {
            int id = tid + i * 256;
            int arr = id >> 9, rem = id & 511, row = rem >> 2, ch = rem & 3;
            const char* src = (const char*)(srcs[arr] + (size_t)row * 512 + kb * 32) + ch * 16;
            uint32_t dst = sb + buf * STG_SZ + arr * STG_ARR + row * 80 + ch * 16;
            cp_async16(dst, src);
        }
        asm volatile("cp.async.commit_group;" ::: "memory");
    };

    load_stage(0, 0);

    for (int kb = 0; kb < 16; kb++) {
        int buf = kb & 1;
        if (kb + 1 < 16) {
            load_stage(kb + 1, buf ^ 1);
            asm volatile("cp.async.wait_group 1;" ::: "memory");
        } else {
            asm volatile("cp.async.wait_group 0;" ::: "memory");
        }
        __syncthreads();

        uint32_t base = sb + buf * STG_SZ;
#pragma unroll
        for (int ks = 0; ks < 2; ks++) {
            uint32_t a_[2][4], b_[4][4];
#pragma unroll
            for (int mi = 0; mi < 2; mi++) {
                uint32_t row = wm * 32 + mi * 16 + (lane & 15);
                uint32_t col = ks * 32 + ((lane >> 4) & 1) * 16;
                ldmatrix_x4(a_[mi], base + row * 80 + col);
            }
#pragma unroll
            for (int p = 0; p < 4; p++) {
                uint32_t row = wn * 64 + p * 16 + (lane & 7) + ((lane >> 4) & 1) * 8;
                uint32_t col = ks * 32 + ((lane >> 3) & 1) * 16;
                ldmatrix_x4(b_[p], base + STG_ARR + row * 80 + col);
            }
#pragma unroll
            for (int mi = 0; mi < 2; mi++)
#pragma unroll
                for (int p = 0; p < 4; p++)
#pragma unroll
                    for (int hf = 0; hf < 2; hf++) {
                        int nb = p * 2 + hf;
                        mma_fp16(c[mi][nb], a_[mi], b_[p][hf * 2], b_[p][hf * 2 + 1]);
                    }
        }
        __syncthreads();
    }

    int grow = mtile * 128 + wm * 32;
    int gcol0 = ntile * 128 + wn * 64;
#pragma unroll
    for (int mi = 0; mi < 2; mi++) {
        int r0 = grow + mi * 16 + (lane >> 2);
#pragma unroll
        for (int nb = 0; nb < 8; nb++) {
            int col = gcol0 + nb * 8 + (lane & 3) * 2;
            if (col < N) {
                float2 v0 = make_float2(c[mi][nb][0], c[mi][nb][1]);
                float2 v1 = make_float2(c[mi][nb][2], c[mi][nb][3]);
                if (res) {
                    float2 q0 = *(const float2*)(res + (size_t)r0 * N + col);
                    float2 q1 = *(const float2*)(res + (size_t)(r0 + 8) * N + col);
                    v0.x += q0.x; v0.y += q0.y; v1.x += q1.x; v1.y += q1.y;
                }
                *(float2*)(C + (size_t)r0 * N + col)       = v0;
                *(float2*)(C + (size_t)(r0 + 8) * N + col) = v1;
            }
        }
    }
}

// ------------------------------------------------------------------ activations (in place; sigmoid(beta) in place)
__global__ __launch_bounds__(256) void act_kernel() {
    int row = blockIdx.x;
    int h = threadIdx.x >> 5, lane = threadIdx.x & 31;
    float* base = g_qkvb + (size_t)row * NQKVB + h * 193;
    {
        float a0 = base[lane], a1 = base[lane + 32];
        float e0 = a0 > 0.f ? a0 + 1.f : expf(a0);
        float e1 = a1 > 0.f ? a1 + 1.f : expf(a1);
        float s = e0 + e1;
#pragma unroll
        for (int off = 16; off > 0; off >>= 1) s += __shfl_xor_sync(0xffffffffu, s, off);
        float inv = 1.f / s;
        base[lane] = e0 * inv; base[lane + 32] = e1 * inv;
    }
    {
        float a0 = base[64 + lane], a1 = base[64 + lane + 32];
        float e0 = a0 > 0.f ? a0 + 1.f : expf(a0);
        float e1 = a1 > 0.f ? a1 + 1.f : expf(a1);
        float s = e0 + e1;
#pragma unroll
        for (int off = 16; off > 0; off >>= 1) s += __shfl_xor_sync(0xffffffffu, s, off);
        float inv = 1.f / s;
        base[64 + lane] = e0 * inv; base[64 + lane + 32] = e1 * inv;
    }
    if (lane == 0) base[192] = 1.f / (1.f + expf(-base[192]));
}

// ------------------------------------------------------------------ chunked delta-rule scan (WY form), C=64, fp16-tiered
#define BST  72        // fp16 smem row stride (elements)
#define BSTB 144       // bytes
#define SST  66        // sS fp32 stride
#define AST  66        // sA fp32 stride
#define RST  64        // sRU fp32 stride (float4-aligned)

// smem byte offsets (all 128-aligned)
#define OFF_S    0
#define OFF_A    16896
#define OFF_RU   33792
#define OFF_BETA 50176
#define OFF_KH   50432
#define OFF_KL   59648
#define OFF_KTH  68864
#define OFF_QH   78080
#define OFF_MH   87296
#define OFF_SUH  96512
#define OFF_SUL  105728
#define SMEM_SCAN 114944

// A split, B single: 2 MMAs
__device__ __forceinline__ void mma64_A2(
    uint32_t Ah, uint32_t Al, uint32_t B, int lane, float c[8][4])
{
#pragma unroll
    for (int ks = 0; ks < 4; ks++) {
        uint32_t ah[4], al[4];
        uint32_t aoff = (uint32_t)(lane & 15) * BSTB + ks * 32 + ((lane >> 4) & 1) * 16;
        ldmatrix_x4(ah, Ah + aoff);
        ldmatrix_x4(al, Al + aoff);
#pragma unroll
        for (int p = 0; p < 4; p++) {
            uint32_t brow = p * 16 + (lane & 7) + ((lane >> 4) & 1) * 8;
            uint32_t boff = brow * BSTB + ks * 32 + ((lane >> 3) & 1) * 16;
            uint32_t b_[4];
            ldmatrix_x4(b_, B + boff);
#pragma unroll
            for (int hf = 0; hf < 2; hf++) {
                int nb = p * 2 + hf;
                mma_fp16(c[nb], ah, b_[hf * 2], b_[hf * 2 + 1]);
                mma_fp16(c[nb], al, b_[hf * 2], b_[hf * 2 + 1]);
            }
        }
    }
}
// A single, B single: 1 MMA
__device__ __forceinline__ void mma64_A1(
    uint32_t A, uint32_t B, int lane, float c[8][4])
{
#pragma unroll
    for (int ks = 0; ks < 4; ks++) {
        uint32_t a_[4];
        uint32_t aoff = (uint32_t)(lane & 15) * BSTB + ks * 32 + ((lane >> 4) & 1) * 16;
        ldmatrix_x4(a_, A + aoff);
#pragma unroll
        for (int p = 0; p < 4; p++) {
            uint32_t brow = p * 16 + (lane & 7) + ((lane >> 4) & 1) * 8;
            uint32_t boff = brow * BSTB + ks * 32 + ((lane >> 3) & 1) * 16;
            uint32_t b_[4];
            ldmatrix_x4(b_, B + boff);
#pragma unroll
            for (int hf = 0; hf < 2; hf++)
                mma_fp16(c[p * 2 + hf], a_, b_[hf * 2], b_[hf * 2 + 1]);
        }
    }
}
// A split, B split: 3 MMAs (drop Al@Bl)
__device__ __forceinline__ void mma64_A2B2(
    uint32_t Ah, uint32_t Al, uint32_t Bh, uint32_t Bl, int lane, float c[8][4])
{
#pragma unroll
    for (int ks = 0; ks < 4; ks++) {
        uint32_t ah[4], al[4];
        uint32_t aoff = (uint32_t)(lane & 15) * BSTB + ks * 32 + ((lane >> 4) & 1) * 16;
        ldmatrix_x4(ah, Ah + aoff);
        ldmatrix_x4(al, Al + aoff);
#pragma unroll
        for (int p = 0; p < 4; p++) {
            uint32_t brow = p * 16 + (lane & 7) + ((lane >> 4) & 1) * 8;
            uint32_t boff = brow * BSTB + ks * 32 + ((lane >> 3) & 1) * 16;
            uint32_t bh[4], bl[4];
            ldmatrix_x4(bh, Bh + boff);
            ldmatrix_x4(bl, Bl + boff);
#pragma unroll
            for (int hf = 0; hf < 2; hf++) {
                int nb = p * 2 + hf;
                mma_fp16(c[nb], ah, bh[hf * 2], bh[hf * 2 + 1]);
                mma_fp16(c[nb], ah, bl[hf * 2], bl[hf * 2 + 1]);
                mma_fp16(c[nb], al, bh[hf * 2], bh[hf * 2 + 1]);
            }
        }
    }
}

__global__ __launch_bounds__(256, 2) void scan_chunked_kernel() {
    extern __shared__ __align__(128) char smem[];
    uint32_t sb = smem_u32(smem);
    int bh = blockIdx.x;
    int b = bh >> 3, h = bh & 7;
    int tid = threadIdx.x, wid = tid >> 5, lane = tid & 31;

    float* sS    = (float*)(smem + OFF_S);
    float* sA    = (float*)(smem + OFF_A);
    float* sRU   = (float*)(smem + OFF_RU);
    float* sBeta = (float*)(smem + OFF_BETA);
    fp16* sKh  = (fp16*)(smem + OFF_KH);
    fp16* sKl  = (fp16*)(smem + OFF_KL);
    fp16* sKTh = (fp16*)(smem + OFF_KTH);
    fp16* sQh  = (fp16*)(smem + OFF_QH);
    fp16* sMh  = (fp16*)(smem + OFF_MH);
    fp16* sSUh = (fp16*)(smem + OFF_SUH);
    fp16* sSUl = (fp16*)(smem + OFF_SUL);

    uint32_t aKh  = sb + OFF_KH,  aKl  = sb + OFF_KL;
    uint32_t aKTh = sb + OFF_KTH;
    uint32_t aQh  = sb + OFF_QH;
    uint32_t aMh  = sb + OFF_MH;
    uint32_t aSUh = sb + OFF_SUH, aSUl = sb + OFF_SUL;

    // zero state S
#pragma unroll
    for (int e = 0; e < 17; e++) {
        int idx = tid + e * 256;
        if (idx < 64 * SST) sS[idx] = 0.f;
    }
    __syncthreads();

    int jm = (wid & 3) * 16;
    int r0 = (lane >> 2);
    int col0 = (lane & 3) * 2;

    for (int cc = 0; cc < 16; cc++) {
        // ---- phase 0: load activated K,Q,V,beta; convert; S -> fp16 hi/lo
#pragma unroll
        for (int r8 = 0; r8 < 8; r8++) {
            int t = wid * 8 + r8;
            const float* src = g_qkvb + ((size_t)((cc * 64 + t) * 32 + b)) * NQKVB + h * 193;
            int j = lane * 2;
            float qx = src[j],       qy = src[j + 1];
            float kx = src[64 + j],  ky = src[64 + j + 1];
            float vx = src[128 + j], vy = src[128 + j + 1];
            // q single
            sQh[t * BST + j]     = __float2half_rn(qx);
            sQh[t * BST + j + 1] = __float2half_rn(qy);
            // k split (+ transposed single)
            fp16 kh0 = __float2half_rn(kx);
            fp16 kh1 = __float2half_rn(ky);
            sKh[t * BST + j] = kh0;     sKh[t * BST + j + 1] = kh1;
            sKl[t * BST + j]     = __float2half_rn(kx - __half2float(kh0));
            sKl[t * BST + j + 1] = __float2half_rn(ky - __half2float(kh1));
            sKTh[j * BST + t] = kh0;    sKTh[(j + 1) * BST + t] = kh1;
            // v fp32
            sRU[t * RST + j] = vx;      sRU[t * RST + j + 1] = vy;
            if (lane == 0) sBeta[t] = src[192];
        }
        // S -> SUh/SUl (fp16 hi/lo)
#pragma unroll
        for (int e = 0; e < 16; e++) {
            int idx = tid + e * 256;
            int i = idx >> 6, j = idx & 63;
            float v = sS[i * SST + j];
            fp16 hv = __float2half_rn(v);
            sSUh[i * BST + j] = hv;
            sSUl[i * BST + j] = __float2half_rn(v - __half2float(hv));
        }
        __syncthreads();

        // ---- phase 1
        float oc[8][4];
#pragma unroll
        for (int nb = 0; nb < 8; nb++)
#pragma unroll
            for (int q = 0; q < 4; q++) oc[nb][q] = 0.f;

        {
            float c1[8][4];
#pragma unroll
            for (int nb = 0; nb < 8; nb++)
#pragma unroll
                for (int q = 0; q < 4; q++) c1[nb][q] = 0.f;

            if (wid < 4) {
                // KK = K K^T  (A split, B single)
                mma64_A2(aKh + jm * BSTB, aKl + jm * BSTB, aKh, lane, c1);
                int t1 = jm + r0, t2 = t1 + 8;
                float b1 = sBeta[t1], b2 = sBeta[t2];
#pragma unroll
                for (int nb = 0; nb < 8; nb++) {
                    int s0 = nb * 8 + col0;
                    sA[t1 * AST + s0]     = (s0     < t1) ? b1 * c1[nb][0] : 0.f;
                    sA[t1 * AST + s0 + 1] = (s0 + 1 < t1) ? b1 * c1[nb][1] : 0.f;
                    sA[t2 * AST + s0]     = (s0     < t2) ? b2 * c1[nb][2] : 0.f;
                    sA[t2 * AST + s0 + 1] = (s0 + 1 < t2) ? b2 * c1[nb][3] : 0.f;
                }
            } else {
                // QK -> M (masked s<=t), single fp16
                mma64_A1(aQh + jm * BSTB, aKh, lane, c1);
                int t1 = jm + r0, t2 = t1 + 8;
#pragma unroll
                for (int nb = 0; nb < 8; nb++) {
                    int s0 = nb * 8 + col0;
#pragma unroll
                    for (int q = 0; q < 4; q++) {
                        int tt = (q >= 2) ? t2 : t1;
                        int ss = s0 + (q & 1);
                        sMh[tt * BST + ss] = __float2half_rn((ss <= tt) ? c1[nb][q] : 0.f);
                    }
                }
            }
            if (wid < 4) {
                float c2[8][4];
#pragma unroll
                for (int nb = 0; nb < 8; nb++)
#pragma unroll
                    for (int q = 0; q < 4; q++) c2[nb][q] = 0.f;
                // KS = K S^T (A split, B split: recurrence)
                mma64_A2B2(aKh + jm * BSTB, aKl + jm * BSTB, aSUh, aSUl, lane, c2);
                int t1 = jm + r0, t2 = t1 + 8;
                float b1 = sBeta[t1], b2 = sBeta[t2];
#pragma unroll
                for (int nb = 0; nb < 8; nb++) {
                    int i0 = nb * 8 + col0;
                    int x11 = t1 * RST + i0, x12 = x11 + 1;
                    int x21 = t2 * RST + i0, x22 = x21 + 1;
                    sRU[x11] = b1 * (sRU[x11] - c2[nb][0]);
                    sRU[x12] = b1 * (sRU[x12] - c2[nb][1]);
                    sRU[x21] = b2 * (sRU[x21] - c2[nb][2]);
                    sRU[x22] = b2 * (sRU[x22] - c2[nb][3]);
                }
            } else {
                // QS = Q S^T -> oc (O path, single A / single B)
                mma64_A1(aQh + jm * BSTB, aSUh, lane, oc);
            }
        }
        __syncthreads();

        // ---- phase 2: blocked forward substitution, U in-place in sRU
        {
            int tl = tid >> 4;
            int ib = (tid & 15) * 4;
            for (int blk = 0; blk < 4; blk++) {
                int T0 = blk * 16;
                if (blk > 0) {
                    int t = T0 + tl;
                    float4 acc = make_float4(0.f, 0.f, 0.f, 0.f);
                    for (int s = 0; s < T0; s++) {
                        float a = sA[t * AST + s];
                        float4 us = *(const float4*)&sRU[s * RST + ib];
                        acc.x += a * us.x; acc.y += a * us.y;
                        acc.z += a * us.z; acc.w += a * us.w;
                    }
                    float4 r = *(float4*)&sRU[t * RST + ib];
                    r.x -= acc.x; r.y -= acc.y; r.z -= acc.z; r.w -= acc.w;
                    *(float4*)&sRU[t * RST + ib] = r;
                }
                __syncthreads();
                if (wid == 0) {
                    float u0[16], u1[16];
#pragma unroll
                    for (int r = 0; r < 16; r++) {
                        int t = T0 + r;
                        float a0 = sRU[t * RST + lane];
                        float a1 = sRU[t * RST + lane + 32];
#pragma unroll
                        for (int s = 0; s < r; s++) {
                            float a = sA[t * AST + T0 + s];
                            a0 -= a * u0[s];
                            a1 -= a * u1[s];
                        }
                        u0[r] = a0; u1[r] = a1;
                        sRU[t * RST + lane] = a0;
                        sRU[t * RST + lane + 32] = a1;
                    }
                }
                __syncthreads();
            }
        }
        // U -> UT fp16 hi/lo (overlay on SU buffers)
#pragma unroll
        for (int e = 0; e < 16; e++) {
            int idx = tid + e * 256;
            int s = idx >> 6, i = idx & 63;
            float v = sRU[s * RST + i];
            fp16 hv = __float2half_rn(v);
            sSUh[i * BST + s] = hv;
            sSUl[i * BST + s] = __float2half_rn(v - __half2float(hv));
        }
        __syncthreads();

        // ---- phase 3
        if (wid >= 4) {
            // O = QS + M U  (M single, U single: O path)
            mma64_A1(aMh + jm * BSTB, aSUh, lane, oc);
            int t1 = jm + r0, t2 = t1 + 8;
            size_t row1 = ((size_t)((cc * 64 + t1) * 32 + b)) * 512 + h * 64;
            size_t row2 = ((size_t)((cc * 64 + t2) * 32 + b)) * 512 + h * 64;
#pragma unroll
            for (int nb = 0; nb < 8; nb++) {
                int i0 = nb * 8 + col0;
#pragma unroll
                for (int q = 0; q < 4; q++) {
                    size_t addr = ((q >= 2) ? row2 : row1) + i0 + (q & 1);
                    g_A2[addr] = __float2half_rn(oc[nb][q]);
                }
            }
        } else {
            // dS = U^T K  (A split, B single: recurrence)
            float c3[8][4];
#pragma unroll
            for (int nb = 0; nb < 8; nb++)
#pragma unroll
                for (int q = 0; q < 4; q++) c3[nb][q] = 0.f;
            mma64_A2(aSUh + jm * BSTB, aSUl + jm * BSTB, aKTh, lane, c3);
            int i1 = jm + r0, i2 = i1 + 8;
#pragma unroll
            for (int nb = 0; nb < 8; nb++) {
                int j0 = nb * 8 + col0;
                sS[i1 * SST + j0]     += c3[nb][0];
                sS[i1 * SST + j0 + 1] += c3[nb][1];
                sS[i2 * SST + j0]     += c3[nb][2];
                sS[i2 * SST + j0 + 1] += c3[nb][3];
            }
        }
        __syncthreads();
    }
}

// ------------------------------------------------------------------ launch
extern "C" void kernel_launch(void* const* d_in, const int* in_sizes, int n_in,
                              void* d_out, int out_size) {
    const float* x     = (const float*)d_in[0];
    const float* gamma = (const float*)d_in[1];
    const float* lnb   = (const float*)d_in[2];
    const float* wslow = (const float*)d_in[3];
    const float* wout  = (const float*)d_in[4];
    float* out = (float*)d_out;

    cudaFuncSetAttribute(gemm_kernel, cudaFuncAttributeMaxDynamicSharedMemorySize, SMEM_DYN);
    cudaFuncSetAttribute(scan_chunked_kernel, cudaFuncAttributeMaxDynamicSharedMemorySize, SMEM_SCAN);

    fp16 *A1, *A2, *B1, *B2;
    cudaGetSymbolAddress((void**)&A1, g_A1);
    cudaGetSymbolAddress((void**)&A2, g_A2);
    cudaGetSymbolAddress((void**)&B1, g_B1);
    cudaGetSymbolAddress((void**)&B2, g_B2);
    float* qkvb;
    cudaGetSymbolAddress((void**)&qkvb, g_qkvb);

    prep_x_kernel<<<ROWS, 128>>>(x, gamma, lnb, A1);
    prep_b_kernel<<<dim3(68, 16), 256>>>(wslow, wout, B1, B2);
    gemm_kernel<<<dim3(NT1, 256), 256, SMEM_DYN>>>(A1, B1, qkvb, nullptr, NQKVB);
    act_kernel<<<ROWS, 256>>>();
    scan_chunked_kernel<<<BSZ * NH, 256, SMEM_SCAN>>>();
    gemm_kernel<<<dim3(NT2, 256), 256, SMEM_DYN>>>(A2, B2, out, x, 512);
}